// round 4
// baseline (speedup 1.0000x reference)
#include <cuda_runtime.h>

#define NNODES 50000
#define NEDGES 800000

// Scratch (allocation-free): device globals, 16B-aligned for vector access.
__device__ __align__(16) float g_cnt[NNODES];        // becomes 1/max(count,1)
__device__ __align__(16) float g_agg[NNODES * 128];  // scatter accumulator
__device__ __align__(16) float g_h1[NNODES * 128];
__device__ __align__(16) float g_h2[NNODES * 64];

// Buffer selectors resolved in device code (no cudaGetSymbolAddress on host).
// SEL: 0 = kernel parameter, 1 = g_h1, 2 = g_h2
template <int SEL>
__device__ __forceinline__ const float* select_src(const float* p) {
    if (SEL == 1) return g_h1;
    if (SEL == 2) return g_h2;
    return p;
}
template <int SEL>
__device__ __forceinline__ float* select_dst(float* p) {
    if (SEL == 1) return g_h1;
    if (SEL == 2) return g_h2;
    return p;
}

__global__ void zero_cnt_kernel() {
    int i = blockIdx.x * blockDim.x + threadIdx.x;
    if (i < NNODES) g_cnt[i] = 0.0f;
}

__global__ void zero_agg_kernel(int n4) {  // n4 = number of float4 to zero
    int i = blockIdx.x * blockDim.x + threadIdx.x;
    if (i < n4) reinterpret_cast<float4*>(g_agg)[i] = make_float4(0.f, 0.f, 0.f, 0.f);
}

// edge_index arrives as int32 (JAX x64 disabled downcasts jnp.int64 -> int32).
__global__ void count_kernel(const int* __restrict__ ei) {
    int e = blockIdx.x * blockDim.x + threadIdx.x;
    if (e < NEDGES) {
        int dst = ei[NEDGES + e];
        atomicAdd(&g_cnt[dst], 1.0f);
    }
}

__global__ void inv_cnt_kernel() {
    int i = blockIdx.x * blockDim.x + threadIdx.x;
    if (i < NNODES) g_cnt[i] = 1.0f / fmaxf(g_cnt[i], 1.0f);
}

// Scatter-add src-features into g_agg[dst]. One thread per (edge, 4-feat chunk).
template <int D, int SRCSEL>
__global__ void scatter_kernel(const float* __restrict__ xp,
                               const int* __restrict__ ei) {
    constexpr int C = D / 4;
    const float* x = select_src<SRCSEL>(xp);
    int tid = blockIdx.x * blockDim.x + threadIdx.x;
    if (tid >= NEDGES * C) return;
    int e = tid / C;
    int c = tid % C;
    int src = ei[e];
    int dst = ei[NEDGES + e];
    float4 v = reinterpret_cast<const float4*>(x)[src * C + c];
    float* d = &g_agg[(size_t)dst * D + c * 4];
    atomicAdd(d + 0, v.x);
    atomicAdd(d + 1, v.y);
    atomicAdd(d + 2, v.z);
    atomicAdd(d + 3, v.w);
}

// Fused: out[n] = (agg[n]*inv_cnt[n]) @ Wl^T + b + x[n] @ Wr^T
// Block = O threads, NB nodes per block. K-tiled weights in smem (padded).
template <int I, int O, int NB, int SRCSEL, int DSTSEL>
__global__ void fused_layer_kernel(const float* __restrict__ xp,
                                   const float* __restrict__ Wl,
                                   const float* __restrict__ b,
                                   const float* __restrict__ Wr,
                                   float* __restrict__ outp) {
    constexpr int KT = 32;
    constexpr int KP = KT + 4;  // 36-float row stride -> conflict-free LDS.128
    __shared__ __align__(16) float xs[NB][I];
    __shared__ __align__(16) float ms[NB][I];
    __shared__ __align__(16) float wl_s[O * KP];
    __shared__ __align__(16) float wr_s[O * KP];

    const float* x = select_src<SRCSEL>(xp);
    float* out = select_dst<DSTSEL>(outp);

    const int t = threadIdx.x;
    const int n0 = blockIdx.x * NB;

    for (int idx = t; idx < NB * I; idx += O) {
        int nb = idx / I, i = idx % I;
        int node = n0 + nb;
        xs[nb][i] = x[(size_t)node * I + i];
        ms[nb][i] = g_agg[(size_t)node * I + i] * g_cnt[node];
    }

    float acc[NB];
#pragma unroll
    for (int nb = 0; nb < NB; nb++) acc[nb] = 0.0f;

    for (int k0 = 0; k0 < I; k0 += KT) {
        __syncthreads();  // previous tile consumed (first iter: xs/ms pending)
        for (int idx = t; idx < O * KT; idx += O) {
            int row = idx / KT, col = idx % KT;
            wl_s[row * KP + col] = Wl[row * I + k0 + col];
            wr_s[row * KP + col] = Wr[row * I + k0 + col];
        }
        __syncthreads();  // W tile + xs/ms visible
#pragma unroll
        for (int k4 = 0; k4 < KT / 4; k4++) {
            float4 wl = *reinterpret_cast<const float4*>(&wl_s[t * KP + k4 * 4]);
            float4 wr = *reinterpret_cast<const float4*>(&wr_s[t * KP + k4 * 4]);
#pragma unroll
            for (int nb = 0; nb < NB; nb++) {
                float4 m  = *reinterpret_cast<const float4*>(&ms[nb][k0 + k4 * 4]);
                float4 xv = *reinterpret_cast<const float4*>(&xs[nb][k0 + k4 * 4]);
                acc[nb] += m.x * wl.x + m.y * wl.y + m.z * wl.z + m.w * wl.w;
                acc[nb] += xv.x * wr.x + xv.y * wr.y + xv.z * wr.z + xv.w * wr.w;
            }
        }
    }

    float bias = b[t];
#pragma unroll
    for (int nb = 0; nb < NB; nb++)
        out[(size_t)(n0 + nb) * O + t] = acc[nb] + bias;
}

extern "C" void kernel_launch(void* const* d_in, const int* in_sizes, int n_in,
                              void* d_out, int out_size) {
    const float* x   = (const float*)d_in[0];
    const int*   ei  = (const int*)d_in[1];   // int32: JAX default (x64 disabled)
    const float* Wl1 = (const float*)d_in[2];
    const float* b1  = (const float*)d_in[3];
    const float* Wr1 = (const float*)d_in[4];
    const float* Wl2 = (const float*)d_in[5];
    const float* b2  = (const float*)d_in[6];
    const float* Wr2 = (const float*)d_in[7];
    const float* Wl3 = (const float*)d_in[8];
    const float* b3  = (const float*)d_in[9];
    const float* Wr3 = (const float*)d_in[10];
    float* out = (float*)d_out;

    const int TB = 256;

    // Degree counts -> inverse (shared by all layers)
    zero_cnt_kernel<<<(NNODES + TB - 1) / TB, TB>>>();
    count_kernel<<<(NEDGES + TB - 1) / TB, TB>>>(ei);
    inv_cnt_kernel<<<(NNODES + TB - 1) / TB, TB>>>();

    // Layer 1: in=128 (x param), out=128 -> g_h1
    zero_agg_kernel<<<(NNODES * 32 + TB - 1) / TB, TB>>>(NNODES * 32);
    scatter_kernel<128, 0><<<(NEDGES * 32 + TB - 1) / TB, TB>>>(x, ei);
    fused_layer_kernel<128, 128, 4, 0, 1><<<NNODES / 4, 128>>>(x, Wl1, b1, Wr1, nullptr);

    // Layer 2: in=128 (g_h1), out=64 -> g_h2
    zero_agg_kernel<<<(NNODES * 32 + TB - 1) / TB, TB>>>(NNODES * 32);
    scatter_kernel<128, 1><<<(NEDGES * 32 + TB - 1) / TB, TB>>>(nullptr, ei);
    fused_layer_kernel<128, 64, 4, 1, 2><<<NNODES / 4, 64>>>(nullptr, Wl2, b2, Wr2, nullptr);

    // Layer 3: in=64 (g_h2), out=128 -> d_out
    zero_agg_kernel<<<(NNODES * 16 + TB - 1) / TB, TB>>>(NNODES * 16);
    scatter_kernel<64, 2><<<(NEDGES * 16 + TB - 1) / TB, TB>>>(nullptr, ei);
    fused_layer_kernel<64, 128, 4, 2, 0><<<NNODES / 4, 128>>>(nullptr, Wl3, b3, Wr3, out);
}

// round 5
// speedup vs baseline: 2.2157x; 2.2157x over previous
#include <cuda_runtime.h>

#define NNODES 50000
#define NEDGES 800000
#define SCAN_T 1024

// ---- device-global scratch (allocation-free) ----
__device__ __align__(16) int   g_deg[NNODES];
__device__ __align__(16) int   g_rowptr[NNODES + 1];
__device__ __align__(16) int   g_cursor[NNODES];
__device__ __align__(16) int   g_csr_src[NEDGES];
__device__ __align__(16) float g_inv[NNODES];          // 1/max(deg,1)
__device__ __align__(16) float g_agg[NNODES * 128];    // mean-aggregated feats
__device__ __align__(16) float g_h1[NNODES * 128];
__device__ __align__(16) float g_h2[NNODES * 64];

// SEL: 0 = kernel parameter, 1 = g_h1, 2 = g_h2 (resolved in device code)
template <int SEL>
__device__ __forceinline__ const float* select_src(const float* p) {
    if (SEL == 1) return g_h1;
    if (SEL == 2) return g_h2;
    return p;
}
template <int SEL>
__device__ __forceinline__ float* select_dst(float* p) {
    if (SEL == 1) return g_h1;
    if (SEL == 2) return g_h2;
    return p;
}

// ---- CSR build (once per launch; edge_index constant across layers) ----
__global__ void zero_deg_kernel() {
    int i = blockIdx.x * blockDim.x + threadIdx.x;
    if (i < NNODES) g_deg[i] = 0;
}

__global__ void count_kernel(const int* __restrict__ ei) {
    int e = blockIdx.x * blockDim.x + threadIdx.x;
    if (e < NEDGES) atomicAdd(&g_deg[ei[NEDGES + e]], 1);
}

// Single-block exclusive scan over 50K degrees; also fills cursor + inv.
__global__ void scan_kernel() {
    __shared__ int partial[SCAN_T];
    const int t = threadIdx.x;
    const int CH = (NNODES + SCAN_T - 1) / SCAN_T;  // 49
    const int base = t * CH;

    int s = 0;
    for (int i = 0; i < CH; i++) {
        int idx = base + i;
        if (idx < NNODES) s += g_deg[idx];
    }
    partial[t] = s;
    __syncthreads();
    // inclusive Hillis-Steele scan over SCAN_T partials
    for (int off = 1; off < SCAN_T; off <<= 1) {
        int add = (t >= off) ? partial[t - off] : 0;
        __syncthreads();
        partial[t] += add;
        __syncthreads();
    }
    int run = (t == 0) ? 0 : partial[t - 1];
    for (int i = 0; i < CH; i++) {
        int idx = base + i;
        if (idx < NNODES) {
            g_rowptr[idx] = run;
            g_cursor[idx] = run;
            int d = g_deg[idx];
            g_inv[idx] = 1.0f / fmaxf((float)d, 1.0f);
            run += d;
        }
    }
    if (t == SCAN_T - 1) g_rowptr[NNODES] = partial[SCAN_T - 1];
}

__global__ void fill_kernel(const int* __restrict__ ei) {
    int e = blockIdx.x * blockDim.x + threadIdx.x;
    if (e < NEDGES) {
        int dst = ei[NEDGES + e];
        int slot = atomicAdd(&g_cursor[dst], 1);
        g_csr_src[slot] = ei[e];
    }
}

// ---- gather-mean: one warp per destination node, coalesced vector loads ----
// D=128 -> float4/lane, D=64 -> float2/lane.
template <int D, int SRCSEL>
__global__ void gather_kernel(const float* __restrict__ xp) {
    const float* x = select_src<SRCSEL>(xp);
    int warp = (blockIdx.x * blockDim.x + threadIdx.x) >> 5;
    int lane = threadIdx.x & 31;
    if (warp >= NNODES) return;
    int beg = g_rowptr[warp];
    int end = g_rowptr[warp + 1];
    float inv = g_inv[warp];

    if (D == 128) {
        float4 acc = make_float4(0.f, 0.f, 0.f, 0.f);
        int j = beg;
        for (; j + 1 < end; j += 2) {
            int s0 = g_csr_src[j], s1 = g_csr_src[j + 1];
            float4 a = reinterpret_cast<const float4*>(x + (size_t)s0 * 128)[lane];
            float4 b = reinterpret_cast<const float4*>(x + (size_t)s1 * 128)[lane];
            acc.x += a.x + b.x; acc.y += a.y + b.y;
            acc.z += a.z + b.z; acc.w += a.w + b.w;
        }
        if (j < end) {
            int s0 = g_csr_src[j];
            float4 a = reinterpret_cast<const float4*>(x + (size_t)s0 * 128)[lane];
            acc.x += a.x; acc.y += a.y; acc.z += a.z; acc.w += a.w;
        }
        acc.x *= inv; acc.y *= inv; acc.z *= inv; acc.w *= inv;
        reinterpret_cast<float4*>(g_agg + (size_t)warp * 128)[lane] = acc;
    } else {
        float2 acc = make_float2(0.f, 0.f);
        int j = beg;
        for (; j + 1 < end; j += 2) {
            int s0 = g_csr_src[j], s1 = g_csr_src[j + 1];
            float2 a = reinterpret_cast<const float2*>(x + (size_t)s0 * 64)[lane];
            float2 b = reinterpret_cast<const float2*>(x + (size_t)s1 * 64)[lane];
            acc.x += a.x + b.x; acc.y += a.y + b.y;
        }
        if (j < end) {
            int s0 = g_csr_src[j];
            float2 a = reinterpret_cast<const float2*>(x + (size_t)s0 * 64)[lane];
            acc.x += a.x; acc.y += a.y;
        }
        acc.x *= inv; acc.y *= inv;
        reinterpret_cast<float2*>(g_agg + (size_t)warp * 64)[lane] = acc;
    }
}

// ---- fused layer: out[n] = agg[n] @ Wl^T + b + x[n] @ Wr^T ----
// Block = O threads, NB nodes/block, K-tiled weights in padded smem.
template <int I, int O, int NB, int SRCSEL, int DSTSEL>
__global__ void fused_layer_kernel(const float* __restrict__ xp,
                                   const float* __restrict__ Wl,
                                   const float* __restrict__ b,
                                   const float* __restrict__ Wr,
                                   float* __restrict__ outp) {
    constexpr int KT = 32;
    constexpr int KP = KT + 4;  // conflict-free LDS.128
    __shared__ __align__(16) float xs[NB][I];
    __shared__ __align__(16) float ms[NB][I];
    __shared__ __align__(16) float wl_s[O * KP];
    __shared__ __align__(16) float wr_s[O * KP];

    const float* x = select_src<SRCSEL>(xp);
    float* out = select_dst<DSTSEL>(outp);

    const int t = threadIdx.x;
    const int n0 = blockIdx.x * NB;

    constexpr int C4 = I / 4;
    for (int idx = t; idx < NB * C4; idx += O) {
        int nb = idx / C4, c = idx % C4;
        int node = n0 + nb;
        reinterpret_cast<float4*>(xs[nb])[c] =
            reinterpret_cast<const float4*>(x + (size_t)node * I)[c];
        reinterpret_cast<float4*>(ms[nb])[c] =
            reinterpret_cast<const float4*>(g_agg + (size_t)node * I)[c];
    }

    float acc[NB];
#pragma unroll
    for (int nb = 0; nb < NB; nb++) acc[nb] = 0.0f;

    for (int k0 = 0; k0 < I; k0 += KT) {
        __syncthreads();
        for (int idx = t; idx < O * KT; idx += O) {
            int row = idx / KT, col = idx % KT;
            wl_s[row * KP + col] = Wl[row * I + k0 + col];
            wr_s[row * KP + col] = Wr[row * I + k0 + col];
        }
        __syncthreads();
#pragma unroll
        for (int k4 = 0; k4 < KT / 4; k4++) {
            float4 wl = *reinterpret_cast<const float4*>(&wl_s[t * KP + k4 * 4]);
            float4 wr = *reinterpret_cast<const float4*>(&wr_s[t * KP + k4 * 4]);
#pragma unroll
            for (int nb = 0; nb < NB; nb++) {
                float4 m  = *reinterpret_cast<const float4*>(&ms[nb][k0 + k4 * 4]);
                float4 xv = *reinterpret_cast<const float4*>(&xs[nb][k0 + k4 * 4]);
                acc[nb] += m.x * wl.x + m.y * wl.y + m.z * wl.z + m.w * wl.w;
                acc[nb] += xv.x * wr.x + xv.y * wr.y + xv.z * wr.z + xv.w * wr.w;
            }
        }
    }

    float bias = b[t];
#pragma unroll
    for (int nb = 0; nb < NB; nb++)
        out[(size_t)(n0 + nb) * O + t] = acc[nb] + bias;
}

extern "C" void kernel_launch(void* const* d_in, const int* in_sizes, int n_in,
                              void* d_out, int out_size) {
    const float* x   = (const float*)d_in[0];
    const int*   ei  = (const int*)d_in[1];   // int32 (JAX x64 disabled)
    const float* Wl1 = (const float*)d_in[2];
    const float* b1  = (const float*)d_in[3];
    const float* Wr1 = (const float*)d_in[4];
    const float* Wl2 = (const float*)d_in[5];
    const float* b2  = (const float*)d_in[6];
    const float* Wr2 = (const float*)d_in[7];
    const float* Wl3 = (const float*)d_in[8];
    const float* b3  = (const float*)d_in[9];
    const float* Wr3 = (const float*)d_in[10];
    float* out = (float*)d_out;

    const int TB = 256;

    // CSR build (once; reused by all 3 layers)
    zero_deg_kernel<<<(NNODES + TB - 1) / TB, TB>>>();
    count_kernel<<<(NEDGES + TB - 1) / TB, TB>>>(ei);
    scan_kernel<<<1, SCAN_T>>>();
    fill_kernel<<<(NEDGES + TB - 1) / TB, TB>>>(ei);

    const int GW = (NNODES * 32 + TB - 1) / TB;  // gather: warp/node, 8 nodes/block

    // Layer 1: in=128 (x), out=128 -> g_h1
    gather_kernel<128, 0><<<GW, TB>>>(x);
    fused_layer_kernel<128, 128, 8, 0, 1><<<NNODES / 8, 128>>>(x, Wl1, b1, Wr1, nullptr);

    // Layer 2: in=128 (g_h1), out=64 -> g_h2
    gather_kernel<128, 1><<<GW, TB>>>(nullptr);
    fused_layer_kernel<128, 64, 8, 1, 2><<<NNODES / 8, 64>>>(nullptr, Wl2, b2, Wr2, nullptr);

    // Layer 3: in=64 (g_h2), out=128 -> d_out
    gather_kernel<64, 2><<<GW, TB>>>(nullptr);
    fused_layer_kernel<64, 128, 8, 2, 0><<<NNODES / 8, 128>>>(nullptr, Wl3, b3, Wr3, out);
}

// round 6
// speedup vs baseline: 3.5785x; 1.6150x over previous
#include <cuda_runtime.h>

#define NNODES 50000
#define NEDGES 800000
#define SCAN_T 1024

// ---- device-global scratch (allocation-free) ----
__device__ __align__(16) int   g_deg[NNODES];
__device__ __align__(16) int   g_rowptr[NNODES + 1];
__device__ __align__(16) int   g_cursor[NNODES];
__device__ __align__(16) int   g_csr_src[NEDGES];
__device__ __align__(16) float g_inv[NNODES];          // 1/max(deg,1)
__device__ __align__(16) float g_z[NNODES * 256];      // [z_l | z_r] stacked
__device__ __align__(16) float g_h1[NNODES * 128];
__device__ __align__(16) float g_h2[NNODES * 64];

// SEL: 0 = kernel parameter, 1 = g_h1, 2 = g_h2 (resolved in device code)
template <int SEL>
__device__ __forceinline__ const float* select_src(const float* p) {
    if (SEL == 1) return g_h1;
    if (SEL == 2) return g_h2;
    return p;
}
template <int SEL>
__device__ __forceinline__ float* select_dst(float* p) {
    if (SEL == 1) return g_h1;
    if (SEL == 2) return g_h2;
    return p;
}

// ---- CSR build (once; edge_index constant across layers) ----
__global__ void zero_deg_kernel() {
    int i = blockIdx.x * blockDim.x + threadIdx.x;
    if (i < NNODES) g_deg[i] = 0;
}

__global__ void count_kernel(const int* __restrict__ ei) {
    int e = blockIdx.x * blockDim.x + threadIdx.x;
    if (e < NEDGES) atomicAdd(&g_deg[ei[NEDGES + e]], 1);
}

__global__ void scan_kernel() {
    __shared__ int partial[SCAN_T];
    const int t = threadIdx.x;
    const int CH = (NNODES + SCAN_T - 1) / SCAN_T;
    const int base = t * CH;

    int s = 0;
    for (int i = 0; i < CH; i++) {
        int idx = base + i;
        if (idx < NNODES) s += g_deg[idx];
    }
    partial[t] = s;
    __syncthreads();
    for (int off = 1; off < SCAN_T; off <<= 1) {
        int add = (t >= off) ? partial[t - off] : 0;
        __syncthreads();
        partial[t] += add;
        __syncthreads();
    }
    int run = (t == 0) ? 0 : partial[t - 1];
    for (int i = 0; i < CH; i++) {
        int idx = base + i;
        if (idx < NNODES) {
            g_rowptr[idx] = run;
            g_cursor[idx] = run;
            g_inv[idx] = 1.0f / fmaxf((float)g_deg[idx], 1.0f);
            run += g_deg[idx];
        }
    }
    if (t == SCAN_T - 1) g_rowptr[NNODES] = partial[SCAN_T - 1];
}

__global__ void fill_kernel(const int* __restrict__ ei) {
    int e = blockIdx.x * blockDim.x + threadIdx.x;
    if (e < NEDGES) {
        int dst = ei[NEDGES + e];
        int slot = atomicAdd(&g_cursor[dst], 1);
        g_csr_src[slot] = ei[e];
    }
}

// ---- SGEMM: z[n][j] = x[n] . W[j]  with W = [Wl ; Wr] stacked (2O rows) ----
// Tile: BM=128 nodes, BN=128 outs, BK=16. 256 threads, 8x8 per thread.
template <int I, int O, int SRCSEL>
__global__ __launch_bounds__(256, 2)
void gemm_kernel(const float* __restrict__ xp,
                 const float* __restrict__ Wl,
                 const float* __restrict__ Wr) {
    __shared__ float as[16][132];  // [k][node], padded
    __shared__ float bs[16][132];  // [k][out]
    const float* x = select_src<SRCSEL>(xp);

    const int t  = threadIdx.x;
    const int m0 = blockIdx.x * 128;
    const int n0 = blockIdx.y * 128;
    const int mi = (t & 15) * 8;
    const int ni = (t >> 4) * 8;

    float acc[8][8];
#pragma unroll
    for (int i = 0; i < 8; i++)
#pragma unroll
        for (int j = 0; j < 8; j++) acc[i][j] = 0.0f;

    for (int k0 = 0; k0 < I; k0 += 16) {
#pragma unroll
        for (int r = 0; r < 2; r++) {
            int f    = t + r * 256;          // 0..511
            int row  = f >> 2;               // 0..127 within tile
            int kq   = (f & 3) * 4;          // 0,4,8,12
            // A tile (x): node-major, float4 along k
            int node = m0 + row;
            float4 av = make_float4(0.f, 0.f, 0.f, 0.f);
            if (node < NNODES)
                av = *reinterpret_cast<const float4*>(x + (size_t)node * I + k0 + kq);
            as[kq + 0][row] = av.x;
            as[kq + 1][row] = av.y;
            as[kq + 2][row] = av.z;
            as[kq + 3][row] = av.w;
            // B tile (weights): row j of [Wl;Wr]
            int j = n0 + row;
            const float* wrow = (j < O) ? (Wl + (size_t)j * I)
                                        : (Wr + (size_t)(j - O) * I);
            float4 bv = *reinterpret_cast<const float4*>(wrow + k0 + kq);
            bs[kq + 0][row] = bv.x;
            bs[kq + 1][row] = bv.y;
            bs[kq + 2][row] = bv.z;
            bs[kq + 3][row] = bv.w;
        }
        __syncthreads();
#pragma unroll
        for (int k = 0; k < 16; k++) {
            float4 a0 = *reinterpret_cast<const float4*>(&as[k][mi]);
            float4 a1 = *reinterpret_cast<const float4*>(&as[k][mi + 4]);
            float4 b0 = *reinterpret_cast<const float4*>(&bs[k][ni]);
            float4 b1 = *reinterpret_cast<const float4*>(&bs[k][ni + 4]);
            float am[8] = {a0.x, a0.y, a0.z, a0.w, a1.x, a1.y, a1.z, a1.w};
            float bn[8] = {b0.x, b0.y, b0.z, b0.w, b1.x, b1.y, b1.z, b1.w};
#pragma unroll
            for (int mm = 0; mm < 8; mm++)
#pragma unroll
                for (int nn = 0; nn < 8; nn++)
                    acc[mm][nn] += am[mm] * bn[nn];
        }
        __syncthreads();
    }

    constexpr int RS = 2 * O;  // z row stride
#pragma unroll
    for (int mm = 0; mm < 8; mm++) {
        int node = m0 + mi + mm;
        if (node < NNODES) {
            float* zr = g_z + (size_t)node * RS + n0 + ni;
            *reinterpret_cast<float4*>(zr + 0) =
                make_float4(acc[mm][0], acc[mm][1], acc[mm][2], acc[mm][3]);
            *reinterpret_cast<float4*>(zr + 4) =
                make_float4(acc[mm][4], acc[mm][5], acc[mm][6], acc[mm][7]);
        }
    }
}

// ---- gather-add: h[n] = inv[n] * sum_{s in N(n)} z_l[s] + z_r[n] + b ----
// One warp per node. O=128 -> float4/lane; O=64 -> float2/lane.
template <int O, int DSTSEL>
__global__ void gather_add_kernel(const float* __restrict__ b,
                                  float* __restrict__ outp) {
    float* out = select_dst<DSTSEL>(outp);
    int warp = (blockIdx.x * blockDim.x + threadIdx.x) >> 5;
    int lane = threadIdx.x & 31;
    if (warp >= NNODES) return;
    int beg = g_rowptr[warp];
    int end = g_rowptr[warp + 1];
    float inv = g_inv[warp];
    constexpr int RS = 2 * O;

    if (O == 128) {
        float4 acc = make_float4(0.f, 0.f, 0.f, 0.f);
        int j = beg;
        for (; j + 3 < end; j += 4) {
            int s0 = g_csr_src[j], s1 = g_csr_src[j + 1];
            int s2 = g_csr_src[j + 2], s3 = g_csr_src[j + 3];
            float4 v0 = reinterpret_cast<const float4*>(g_z + (size_t)s0 * RS)[lane];
            float4 v1 = reinterpret_cast<const float4*>(g_z + (size_t)s1 * RS)[lane];
            float4 v2 = reinterpret_cast<const float4*>(g_z + (size_t)s2 * RS)[lane];
            float4 v3 = reinterpret_cast<const float4*>(g_z + (size_t)s3 * RS)[lane];
            acc.x += (v0.x + v1.x) + (v2.x + v3.x);
            acc.y += (v0.y + v1.y) + (v2.y + v3.y);
            acc.z += (v0.z + v1.z) + (v2.z + v3.z);
            acc.w += (v0.w + v1.w) + (v2.w + v3.w);
        }
        for (; j < end; j++) {
            int s0 = g_csr_src[j];
            float4 v0 = reinterpret_cast<const float4*>(g_z + (size_t)s0 * RS)[lane];
            acc.x += v0.x; acc.y += v0.y; acc.z += v0.z; acc.w += v0.w;
        }
        float4 zr = reinterpret_cast<const float4*>(g_z + (size_t)warp * RS + O)[lane];
        float4 bb = reinterpret_cast<const float4*>(b)[lane];
        float4 res;
        res.x = acc.x * inv + zr.x + bb.x;
        res.y = acc.y * inv + zr.y + bb.y;
        res.z = acc.z * inv + zr.z + bb.z;
        res.w = acc.w * inv + zr.w + bb.w;
        reinterpret_cast<float4*>(out + (size_t)warp * O)[lane] = res;
    } else {
        float2 acc = make_float2(0.f, 0.f);
        int j = beg;
        for (; j + 3 < end; j += 4) {
            int s0 = g_csr_src[j], s1 = g_csr_src[j + 1];
            int s2 = g_csr_src[j + 2], s3 = g_csr_src[j + 3];
            float2 v0 = reinterpret_cast<const float2*>(g_z + (size_t)s0 * RS)[lane];
            float2 v1 = reinterpret_cast<const float2*>(g_z + (size_t)s1 * RS)[lane];
            float2 v2 = reinterpret_cast<const float2*>(g_z + (size_t)s2 * RS)[lane];
            float2 v3 = reinterpret_cast<const float2*>(g_z + (size_t)s3 * RS)[lane];
            acc.x += (v0.x + v1.x) + (v2.x + v3.x);
            acc.y += (v0.y + v1.y) + (v2.y + v3.y);
        }
        for (; j < end; j++) {
            int s0 = g_csr_src[j];
            float2 v0 = reinterpret_cast<const float2*>(g_z + (size_t)s0 * RS)[lane];
            acc.x += v0.x; acc.y += v0.y;
        }
        float2 zr = reinterpret_cast<const float2*>(g_z + (size_t)warp * RS + O)[lane];
        float2 bb = reinterpret_cast<const float2*>(b)[lane];
        float2 res;
        res.x = acc.x * inv + zr.x + bb.x;
        res.y = acc.y * inv + zr.y + bb.y;
        reinterpret_cast<float2*>(out + (size_t)warp * O)[lane] = res;
    }
}

extern "C" void kernel_launch(void* const* d_in, const int* in_sizes, int n_in,
                              void* d_out, int out_size) {
    const float* x   = (const float*)d_in[0];
    const int*   ei  = (const int*)d_in[1];   // int32 (JAX x64 disabled)
    const float* Wl1 = (const float*)d_in[2];
    const float* b1  = (const float*)d_in[3];
    const float* Wr1 = (const float*)d_in[4];
    const float* Wl2 = (const float*)d_in[5];
    const float* b2  = (const float*)d_in[6];
    const float* Wr2 = (const float*)d_in[7];
    const float* Wl3 = (const float*)d_in[8];
    const float* b3  = (const float*)d_in[9];
    const float* Wr3 = (const float*)d_in[10];
    float* out = (float*)d_out;

    const int TB = 256;
    const int MT = (NNODES + 127) / 128;  // 391 M-tiles
    const int GW = (NNODES * 32 + TB - 1) / TB;  // gather: warp/node

    // CSR build
    zero_deg_kernel<<<(NNODES + TB - 1) / TB, TB>>>();
    count_kernel<<<(NEDGES + TB - 1) / TB, TB>>>(ei);
    scan_kernel<<<1, SCAN_T>>>();
    fill_kernel<<<(NEDGES + TB - 1) / TB, TB>>>(ei);

    // Layer 1: I=128, O=128. z = x @ [Wl1|Wr1]^T ; h1 = gather-add
    gemm_kernel<128, 128, 0><<<dim3(MT, 2), 256>>>(x, Wl1, Wr1);
    gather_add_kernel<128, 1><<<GW, TB>>>(b1, nullptr);

    // Layer 2: I=128, O=64
    gemm_kernel<128, 64, 1><<<dim3(MT, 1), 256>>>(nullptr, Wl2, Wr2);
    gather_add_kernel<64, 2><<<GW, TB>>>(b2, nullptr);

    // Layer 3: I=64, O=128
    gemm_kernel<64, 128, 2><<<dim3(MT, 2), 256>>>(nullptr, Wl3, Wr3);
    gather_add_kernel<128, 0><<<GW, TB>>>(b3, out);
}